// round 8
// baseline (speedup 1.0000x reference)
#include <cuda_runtime.h>

// Work in log2 units; clamp -100 (nat log) = -100/ln2 in log2 units.
#define LG2_CLAMP (-144.26950408889634f)
#define LN2       (0.6931471805599453f)

// Cross-replay scratch: last block resets both to 0, so every graph replay
// starts from a clean state (initial static value is 0).
__device__ float        g_acc   = 0.0f;
__device__ unsigned int g_count = 0u;

__device__ __forceinline__ float lg2_fast(float x) {
    float r;
    asm("lg2.approx.f32 %0, %1;" : "=f"(r) : "f"(x));
    return r;
}

struct f8 { float4 a, b; };

// 256-bit streaming load (Blackwell LDG.E.256), evict-first.
__device__ __forceinline__ f8 ldcs8(const float* p) {
    f8 v;
    asm volatile("ld.global.cs.v8.f32 {%0,%1,%2,%3,%4,%5,%6,%7}, [%8];"
                 : "=f"(v.a.x), "=f"(v.a.y), "=f"(v.a.z), "=f"(v.a.w),
                   "=f"(v.b.x), "=f"(v.b.y), "=f"(v.b.z), "=f"(v.b.w)
                 : "l"(p));
    return v;
}

__device__ __forceinline__ float bce4_lg2(float4 p, float4 t) {
    float lp0 = fmaxf(lg2_fast(p.x),        LG2_CLAMP);
    float lq0 = fmaxf(lg2_fast(1.0f - p.x), LG2_CLAMP);
    float lp1 = fmaxf(lg2_fast(p.y),        LG2_CLAMP);
    float lq1 = fmaxf(lg2_fast(1.0f - p.y), LG2_CLAMP);
    float lp2 = fmaxf(lg2_fast(p.z),        LG2_CLAMP);
    float lq2 = fmaxf(lg2_fast(1.0f - p.z), LG2_CLAMP);
    float lp3 = fmaxf(lg2_fast(p.w),        LG2_CLAMP);
    float lq3 = fmaxf(lg2_fast(1.0f - p.w), LG2_CLAMP);
    float s = lq0 + t.x * (lp0 - lq0);
    s += lq1 + t.y * (lp1 - lq1);
    s += lq2 + t.z * (lp2 - lq2);
    s += lq3 + t.w * (lp3 - lq3);
    return s;
}

__global__ void __launch_bounds__(256)
vloss_main(const float* __restrict__ pred,
           const float* __restrict__ tru,
           float* __restrict__ out,
           int n8, float inv_scale) {
    float acc = 0.0f;
    const int tid    = blockIdx.x * blockDim.x + threadIdx.x;
    const int stride = gridDim.x * blockDim.x;   // in units of 8 floats

    // Unroll x2 of 256-bit loads: 4 independent LDG.256 front-batched
    // (4KB/warp in flight, half the issue slots of the LDG.128 version).
    int i = tid;
    const int stride2 = stride * 2;
    for (; i + stride < n8; i += stride2) {
        f8 pa = ldcs8(pred + (size_t)i * 8);
        f8 pb = ldcs8(pred + (size_t)(i + stride) * 8);
        f8 ta = ldcs8(tru  + (size_t)i * 8);
        f8 tb = ldcs8(tru  + (size_t)(i + stride) * 8);

        acc -= bce4_lg2(pa.a, ta.a);
        acc -= bce4_lg2(pa.b, ta.b);
        acc -= bce4_lg2(pb.a, tb.a);
        acc -= bce4_lg2(pb.b, tb.b);
    }
    // Remainder
    for (; i < n8; i += stride) {
        f8 p = ldcs8(pred + (size_t)i * 8);
        f8 t = ldcs8(tru  + (size_t)i * 8);
        acc -= bce4_lg2(p.a, t.a);
        acc -= bce4_lg2(p.b, t.b);
    }

    // warp reduce
    #pragma unroll
    for (int off = 16; off > 0; off >>= 1)
        acc += __shfl_down_sync(0xFFFFFFFFu, acc, off);

    __shared__ float warp_sums[8];
    int lane = threadIdx.x & 31;
    int wid  = threadIdx.x >> 5;
    if (lane == 0) warp_sums[wid] = acc;
    __syncthreads();

    if (wid == 0 && lane == 0) {
        float v = 0.0f;
        #pragma unroll
        for (int w = 0; w < 8; w++) v += warp_sums[w];

        // Accumulate block partial into device-global scalar.
        atomicAdd(&g_acc, v);
        __threadfence();

        // Ticket: last block finalizes the output and resets state so the
        // next graph replay starts clean.
        unsigned int ticket = atomicAdd(&g_count, 1u);
        if (ticket == gridDim.x - 1) {
            *out = g_acc * inv_scale;
            g_acc   = 0.0f;
            g_count = 0u;
        }
    }
}

extern "C" void kernel_launch(void* const* d_in, const int* in_sizes, int n_in,
                              void* d_out, int out_size) {
    const float* pred = (const float*)d_in[0];
    const float* tru  = (const float*)d_in[1];
    float* out = (float*)d_out;

    int n = in_sizes[0];               // 33,554,432 (divisible by 8)
    int n8 = n >> 3;                   // 256-bit chunk count
    // divisor: H * B = 65536 * 64; multiply by ln2 to convert log2 -> ln
    float inv_scale = LN2 / (65536.0f * 64.0f);

    int threads = 256;
    int blocks = 148 * 16;             // 2368 blocks: measured-best concurrency
    vloss_main<<<blocks, threads>>>(pred, tru, out, n8, inv_scale);
}